// round 1
// baseline (speedup 1.0000x reference)
#include <cuda_runtime.h>
#include <math.h>

// ---------------- problem constants ----------------
namespace {
constexpr int kN   = 50625;          // SIDE^4
constexpr int kB   = 16;             // batch
constexpr int kDim = 16;
constexpr int kH   = 8;
constexpr int kDH  = 4;
constexpr int kFFD = 64;
constexpr int kBot = 26;
constexpr int kL   = 6;
constexpr int kTPB = 256;
constexpr int kBPB = (kN + kTPB - 1) / kTPB;   // 198 blocks per batch
constexpr int kGrid = kB * kBPB;               // 3168
constexpr float kScale = 0.5f;                 // DH^-0.5
}

// ---------------- scratch (device globals; no allocation) ----------------
__device__ float g_x[(size_t)kB * kN * kDim];      // token states, 51.8 MB
__device__ float g_partQ[kGrid * 40];              // per-block partial sums (stage A)
__device__ float g_partK[kGrid * 40];              // per-block partial sums (stage B)

// ---------------- helpers ----------------
__device__ __forceinline__ void ln16(const float* x, const float* g,
                                     const float* bb, float* y) {
  float m = 0.f;
#pragma unroll
  for (int d = 0; d < 16; d++) m += x[d];
  m *= (1.f / 16.f);
  float v = 0.f;
#pragma unroll
  for (int d = 0; d < 16; d++) { float t = x[d] - m; v = fmaf(t, t, v); }
  v *= (1.f / 16.f);
  float r = rsqrtf(v + 1e-5f);
#pragma unroll
  for (int d = 0; d < 16; d++) y[d] = (x[d] - m) * r * g[d] + bb[d];
}

// rotary cos/sin reproducing fp32 semantics of cos(fl32(n*pi32)), etc.
// cos(n*pi + delta) = (-1)^n cos(delta);  delta computed in double, tiny.
__device__ __forceinline__ void rot_cs(int n, float& c0, float& s0,
                                       float& c1, float& s1) {
  float nf = (float)n;
  float p0 = nf * 3.14159265358979323846f;   // fl32(n * fl32(pi))
  float p1 = nf * 15.70796326794896619231f;  // fl32(n * fl32(5*pi))
  double d0 = (double)p0 - (double)n * 3.14159265358979323846;
  double d1 = (double)p1 - (double)n * 15.70796326794896619231;
  float e0 = (float)d0, e1 = (float)d1;
  float sgn = (n & 1) ? -1.f : 1.f;          // parity of n == parity of 5n
  c0 = sgn * (1.f - 0.5f * e0 * e0);
  s0 = sgn * e0 * (1.f - 0.1666666667f * e0 * e0);
  c1 = sgn * (1.f - 0.5f * e1 * e1);
  s1 = sgn * e1 * (1.f - 0.1666666667f * e1 * e1);
}

// deterministic block reduction of 40 per-thread floats -> 40 global floats
__device__ __forceinline__ void reduce40(float* vals, float* out) {
  __shared__ float s_red[8][40];
  int lane = threadIdx.x & 31, w = threadIdx.x >> 5;
#pragma unroll
  for (int k = 0; k < 40; k++) {
    float v = vals[k];
    v += __shfl_down_sync(0xffffffffu, v, 16);
    v += __shfl_down_sync(0xffffffffu, v, 8);
    v += __shfl_down_sync(0xffffffffu, v, 4);
    v += __shfl_down_sync(0xffffffffu, v, 2);
    v += __shfl_down_sync(0xffffffffu, v, 1);
    if (lane == 0) s_red[w][k] = v;
  }
  __syncthreads();
  if (threadIdx.x < 40) {
    float s = 0.f;
#pragma unroll
    for (int w2 = 0; w2 < 8; w2++) s += s_red[w2][threadIdx.x];
    out[threadIdx.x] = s;
  }
}

// dot of y[16] with transposed weight row (contiguous 16 floats, float4 loads)
__device__ __forceinline__ float dot16(const float* y, const float* wrow) {
  float a = 0.f;
#pragma unroll
  for (int d4 = 0; d4 < 4; d4++) {
    float4 w = *reinterpret_cast<const float4*>(wrow + 4 * d4);
    a = fmaf(y[4*d4+0], w.x, a);
    a = fmaf(y[4*d4+1], w.y, a);
    a = fmaf(y[4*d4+2], w.z, a);
    a = fmaf(y[4*d4+3], w.w, a);
  }
  return a;
}

// ---------------- kernels ----------------
__global__ void __launch_bounds__(kTPB) embed_kernel(
    const float* __restrict__ corr, const float* __restrict__ W_emb,
    const float* __restrict__ b_emb) {
  __shared__ float sW[kBot * kDim];
  __shared__ float sb[kDim];
  for (int i = threadIdx.x; i < kBot * kDim; i += kTPB) sW[i] = W_emb[i];
  if (threadIdx.x < kDim) sb[threadIdx.x] = b_emb[threadIdx.x];
  __syncthreads();
  int b = blockIdx.x / kBPB;
  int n = (blockIdx.x % kBPB) * kTPB + threadIdx.x;
  if (n >= kN) return;
  float x[kDim];
#pragma unroll
  for (int d = 0; d < kDim; d++) x[d] = sb[d];
  const float* cp = corr + (size_t)b * kBot * kN + n;
#pragma unroll 13
  for (int c = 0; c < kBot; c++) {
    float v = fmaxf(cp[(size_t)c * kN], 0.f);
#pragma unroll
    for (int d4 = 0; d4 < 4; d4++) {
      float4 w = *reinterpret_cast<const float4*>(&sW[c * kDim + 4 * d4]);
      x[4*d4+0] = fmaf(v, w.x, x[4*d4+0]);
      x[4*d4+1] = fmaf(v, w.y, x[4*d4+1]);
      x[4*d4+2] = fmaf(v, w.z, x[4*d4+2]);
      x[4*d4+3] = fmaf(v, w.w, x[4*d4+3]);
    }
  }
  float* xp = g_x + (size_t)(b * kN + n) * kDim;
#pragma unroll
  for (int d = 0; d < kDim; d += 4)
    *reinterpret_cast<float4*>(xp + d) = make_float4(x[d], x[d+1], x[d+2], x[d+3]);
}

// Stage A: per-token q, rotary-q, q-logit; block-partial softmax stats
__global__ void __launch_bounds__(kTPB) stageA_kernel(
    const float* __restrict__ Wqkv, const float* __restrict__ ln1g,
    const float* __restrict__ ln1b, const float* __restrict__ wqlog) {
  __shared__ float sW[32 * 16];   // transposed: [col][dim]
  __shared__ float sg[16], sb[16], swq[4];
  for (int i = threadIdx.x; i < 512; i += kTPB) {
    int c = i >> 4, d = i & 15;
    sW[i] = Wqkv[d * 96 + c];     // q cols 0..31
  }
  if (threadIdx.x < 16) { sg[threadIdx.x] = ln1g[threadIdx.x]; sb[threadIdx.x] = ln1b[threadIdx.x]; }
  if (threadIdx.x < 4) swq[threadIdx.x] = wqlog[threadIdx.x];
  __syncthreads();
  int b = blockIdx.x / kBPB;
  int n = (blockIdx.x % kBPB) * kTPB + threadIdx.x;
  float vals[40];
#pragma unroll
  for (int k = 0; k < 40; k++) vals[k] = 0.f;
  if (n < kN) {
    const float* xp = g_x + (size_t)(b * kN + n) * kDim;
    float x[16], y[16];
#pragma unroll
    for (int d = 0; d < 16; d += 4) {
      float4 t = *reinterpret_cast<const float4*>(xp + d);
      x[d] = t.x; x[d+1] = t.y; x[d+2] = t.z; x[d+3] = t.w;
    }
    ln16(x, sg, sb, y);
    float c0, s0, c1, s1; rot_cs(n, c0, s0, c1, s1);
#pragma unroll
    for (int h = 0; h < 8; h++) {
      float q0 = dot16(y, &sW[(4*h+0)*16]);
      float q1 = dot16(y, &sW[(4*h+1)*16]);
      float q2 = dot16(y, &sW[(4*h+2)*16]);
      float q3 = dot16(y, &sW[(4*h+3)*16]);
      float lg = (q0*swq[0] + q1*swq[1] + q2*swq[2] + q3*swq[3]) * kScale;
      float e = expf(lg);
      float r0 = q0*c0 - q1*s0, r1 = q1*c0 + q0*s0;
      float r2 = q2*c1 - q3*s1, r3 = q3*c1 + q2*s1;
      vals[h*5+0] = e;
      vals[h*5+1] = e*r0; vals[h*5+2] = e*r1;
      vals[h*5+3] = e*r2; vals[h*5+4] = e*r3;
    }
  }
  reduce40(vals, g_partQ + (size_t)blockIdx.x * 40);
}

// Stage B: finish q-softmax (global_q), per-token k, k2 logits; partial stats
__global__ void __launch_bounds__(kTPB) stageB_kernel(
    const float* __restrict__ Wqkv, const float* __restrict__ ln1g,
    const float* __restrict__ ln1b, const float* __restrict__ wklog) {
  __shared__ float sW[32 * 16];   // transposed k cols
  __shared__ float sg[16], sb[16], swk[2];
  __shared__ float sgq[32];       // global_q [h][d]
  for (int i = threadIdx.x; i < 512; i += kTPB) {
    int c = i >> 4, d = i & 15;
    sW[i] = Wqkv[d * 96 + 32 + c];
  }
  if (threadIdx.x < 16) { sg[threadIdx.x] = ln1g[threadIdx.x]; sb[threadIdx.x] = ln1b[threadIdx.x]; }
  if (threadIdx.x < 2) swk[threadIdx.x] = wklog[threadIdx.x];
  int b = blockIdx.x / kBPB;
  if (threadIdx.x < 32) {
    int h = threadIdx.x >> 2, d = threadIdx.x & 3;
    float den = 0.f, num = 0.f;
    const float* pp = g_partQ + (size_t)b * kBPB * 40;
    for (int blk = 0; blk < kBPB; blk++) {
      den += pp[blk*40 + h*5];
      num += pp[blk*40 + h*5 + 1 + d];
    }
    sgq[threadIdx.x] = num / den;
  }
  __syncthreads();
  int n = (blockIdx.x % kBPB) * kTPB + threadIdx.x;
  float vals[40];
#pragma unroll
  for (int k = 0; k < 40; k++) vals[k] = 0.f;
  if (n < kN) {
    const float* xp = g_x + (size_t)(b * kN + n) * kDim;
    float x[16], y[16];
#pragma unroll
    for (int d = 0; d < 16; d += 4) {
      float4 t = *reinterpret_cast<const float4*>(xp + d);
      x[d] = t.x; x[d+1] = t.y; x[d+2] = t.z; x[d+3] = t.w;
    }
    ln16(x, sg, sb, y);
    float c0, s0, c1, s1; rot_cs(n, c0, s0, c1, s1);
#pragma unroll
    for (int h = 0; h < 8; h++) {
      float k0 = dot16(y, &sW[(4*h+0)*16]);
      float k1 = dot16(y, &sW[(4*h+1)*16]);
      float k2v = dot16(y, &sW[(4*h+2)*16]);
      float k3 = dot16(y, &sW[(4*h+3)*16]);
      float p0 = k0*sgq[4*h+0] + k1*sgq[4*h+1];
      float p1 = k2v*sgq[4*h+2] + k3*sgq[4*h+3];
      float lg = (p0*swk[0] + p1*swk[1]) * kScale;
      float e = expf(lg);
      float r0 = k0*c0 - k1*s0, r1 = k1*c0 + k0*s0;
      float r2 = k2v*c1 - k3*s1, r3 = k3*c1 + k2v*s1;
      vals[h*5+0] = e;
      vals[h*5+1] = e*r0; vals[h*5+2] = e*r1;
      vals[h*5+3] = e*r2; vals[h*5+4] = e*r3;
    }
  }
  reduce40(vals, g_partK + (size_t)blockIdx.x * 40);
}

// Stage C: finish k-softmax (global_k), attention output, residual, FF, residual
__global__ void __launch_bounds__(kTPB) stageC_kernel(
    const float* __restrict__ Wqkv, const float* __restrict__ ln1g,
    const float* __restrict__ ln1b,
    const float* __restrict__ Wr, const float* __restrict__ br,
    const float* __restrict__ Wo, const float* __restrict__ bo,
    const float* __restrict__ ln2g, const float* __restrict__ ln2b,
    const float* __restrict__ W1, const float* __restrict__ b1,
    const float* __restrict__ W2, const float* __restrict__ b2,
    const float* __restrict__ Wout, const float* __restrict__ bout,
    float* __restrict__ out, int last) {
  __shared__ float sWq[32 * 16], sWv[32 * 16];   // transposed
  __shared__ float sWo[32 * 16];                 // natural [c][d]
  __shared__ float sW1[64 * 16];                 // transposed [j][d]
  __shared__ float sW2[64 * 16];                 // natural [j][d]
  __shared__ float sg1[16], sb1g[16], sg2[16], sb2g[16];
  __shared__ float sWr[8], sbr[4], sbo[16], sB1[64], sB2[16];
  __shared__ float sgk[32], swout[16];
  __shared__ float sbout;

  for (int i = threadIdx.x; i < 512; i += kTPB) {
    int c = i >> 4, d = i & 15;
    sWq[i] = Wqkv[d * 96 + c];
    sWv[i] = Wqkv[d * 96 + 64 + c];
    sWo[i] = Wo[i];                 // (32,16) row-major: row c contiguous in d
  }
  for (int i = threadIdx.x; i < 1024; i += kTPB) {
    int j = i >> 4, d = i & 15;
    sW1[i] = W1[d * 64 + j];        // transpose (16,64) -> [j][d]
    sW2[i] = W2[i];                 // (64,16) row-major
  }
  if (threadIdx.x < 16) {
    int i = threadIdx.x;
    sg1[i] = ln1g[i]; sb1g[i] = ln1b[i];
    sg2[i] = ln2g[i]; sb2g[i] = ln2b[i];
    sbo[i] = bo[i]; sB2[i] = b2[i]; swout[i] = Wout[i];
  }
  if (threadIdx.x < 64) sB1[threadIdx.x] = b1[threadIdx.x];
  if (threadIdx.x < 8) sWr[threadIdx.x] = Wr[threadIdx.x];
  if (threadIdx.x < 4) sbr[threadIdx.x] = br[threadIdx.x];
  if (threadIdx.x == 0) sbout = bout[0];
  int b = blockIdx.x / kBPB;
  if (threadIdx.x >= 64 && threadIdx.x < 96) {
    int t = threadIdx.x - 64;
    int h = t >> 2, d = t & 3;
    float den = 0.f, num = 0.f;
    const float* pp = g_partK + (size_t)b * kBPB * 40;
    for (int blk = 0; blk < kBPB; blk++) {
      den += pp[blk*40 + h*5];
      num += pp[blk*40 + h*5 + 1 + d];
    }
    sgk[t] = num / den;
  }
  __syncthreads();

  int n = (blockIdx.x % kBPB) * kTPB + threadIdx.x;
  if (n >= kN) return;

  float* xp = g_x + (size_t)(b * kN + n) * kDim;
  float x[16], y[16];
#pragma unroll
  for (int d = 0; d < 16; d += 4) {
    float4 t = *reinterpret_cast<const float4*>(xp + d);
    x[d] = t.x; x[d+1] = t.y; x[d+2] = t.z; x[d+3] = t.w;
  }
  ln16(x, sg1, sb1g, y);

  // attention value path per head
  float r[32];
#pragma unroll
  for (int h = 0; h < 8; h++) {
    float q0 = dot16(y, &sWq[(4*h+0)*16]);
    float q1 = dot16(y, &sWq[(4*h+1)*16]);
    float q2 = dot16(y, &sWq[(4*h+2)*16]);
    float q3 = dot16(y, &sWq[(4*h+3)*16]);
    float v0 = dot16(y, &sWv[(4*h+0)*16]);
    float v1 = dot16(y, &sWv[(4*h+1)*16]);
    float v2 = dot16(y, &sWv[(4*h+2)*16]);
    float v3 = dot16(y, &sWv[(4*h+3)*16]);
    float u0 = v0*sgk[4*h+0] + v1*sgk[4*h+1];
    float u1 = v2*sgk[4*h+2] + v3*sgk[4*h+3];
    r[4*h+0] = fmaf(u0, sWr[0], fmaf(u1, sWr[4], sbr[0])) + q0;
    r[4*h+1] = fmaf(u0, sWr[1], fmaf(u1, sWr[5], sbr[1])) + q1;
    r[4*h+2] = fmaf(u0, sWr[2], fmaf(u1, sWr[6], sbr[2])) + q2;
    r[4*h+3] = fmaf(u0, sWr[3], fmaf(u1, sWr[7], sbr[3])) + q3;
  }

  // x += r @ W_o + b_o
  float acc[16];
#pragma unroll
  for (int d = 0; d < 16; d++) acc[d] = sbo[d];
#pragma unroll
  for (int c = 0; c < 32; c++) {
    float rc = r[c];
#pragma unroll
    for (int d4 = 0; d4 < 4; d4++) {
      float4 w = *reinterpret_cast<const float4*>(&sWo[c * 16 + 4 * d4]);
      acc[4*d4+0] = fmaf(rc, w.x, acc[4*d4+0]);
      acc[4*d4+1] = fmaf(rc, w.y, acc[4*d4+1]);
      acc[4*d4+2] = fmaf(rc, w.z, acc[4*d4+2]);
      acc[4*d4+3] = fmaf(rc, w.w, acc[4*d4+3]);
    }
  }
#pragma unroll
  for (int d = 0; d < 16; d++) x[d] += acc[d];

  // FF block
  float y2[16];
  ln16(x, sg2, sb2g, y2);
#pragma unroll
  for (int d = 0; d < 16; d++) acc[d] = sB2[d];
#pragma unroll 8
  for (int j = 0; j < 64; j++) {
    float p = sB1[j] + dot16(y2, &sW1[j * 16]);
    float hj = 0.5f * p * (1.f + erff(p * 0.7071067811865475f));
#pragma unroll
    for (int d4 = 0; d4 < 4; d4++) {
      float4 w = *reinterpret_cast<const float4*>(&sW2[j * 16 + 4 * d4]);
      acc[4*d4+0] = fmaf(hj, w.x, acc[4*d4+0]);
      acc[4*d4+1] = fmaf(hj, w.y, acc[4*d4+1]);
      acc[4*d4+2] = fmaf(hj, w.z, acc[4*d4+2]);
      acc[4*d4+3] = fmaf(hj, w.w, acc[4*d4+3]);
    }
  }
#pragma unroll
  for (int d = 0; d < 16; d++) x[d] += acc[d];

  if (last) {
    float o = sbout;
#pragma unroll
    for (int d = 0; d < 16; d++) o = fmaf(x[d], swout[d], o);
    out[(size_t)b * kN + n] = o;
  } else {
#pragma unroll
    for (int d = 0; d < 16; d += 4)
      *reinterpret_cast<float4*>(xp + d) = make_float4(x[d], x[d+1], x[d+2], x[d+3]);
  }
}

// ---------------- host launcher ----------------
extern "C" void kernel_launch(void* const* d_in, const int* in_sizes, int n_in,
                              void* d_out, int out_size) {
  (void)in_sizes; (void)n_in; (void)out_size;
  const float* corr  = (const float*)d_in[0];
  const float* W_emb = (const float*)d_in[1];
  const float* b_emb = (const float*)d_in[2];
  const float* ln1_g = (const float*)d_in[3];
  const float* ln1_b = (const float*)d_in[4];
  const float* W_qkv = (const float*)d_in[5];
  const float* w_qlog= (const float*)d_in[6];
  const float* w_klog= (const float*)d_in[7];
  const float* W_r   = (const float*)d_in[8];
  const float* b_r   = (const float*)d_in[9];
  const float* W_o   = (const float*)d_in[10];
  const float* b_o   = (const float*)d_in[11];
  const float* ln2_g = (const float*)d_in[12];
  const float* ln2_b = (const float*)d_in[13];
  const float* W_ff1 = (const float*)d_in[14];
  const float* b_ff1 = (const float*)d_in[15];
  const float* W_ff2 = (const float*)d_in[16];
  const float* b_ff2 = (const float*)d_in[17];
  const float* W_out = (const float*)d_in[18];
  const float* b_out = (const float*)d_in[19];
  float* out = (float*)d_out;

  embed_kernel<<<kGrid, kTPB>>>(corr, W_emb, b_emb);
  for (int i = 0; i < kL; i++) {
    const float* Wq = W_qkv + (size_t)i * 16 * 96;
    stageA_kernel<<<kGrid, kTPB>>>(Wq, ln1_g + i*16, ln1_b + i*16, w_qlog + i*4);
    stageB_kernel<<<kGrid, kTPB>>>(Wq, ln1_g + i*16, ln1_b + i*16, w_klog + i*2);
    stageC_kernel<<<kGrid, kTPB>>>(Wq, ln1_g + i*16, ln1_b + i*16,
        W_r + i*8, b_r + i*4, W_o + i*512, b_o + i*16,
        ln2_g + i*16, ln2_b + i*16,
        W_ff1 + (size_t)i*16*64, b_ff1 + i*64,
        W_ff2 + (size_t)i*64*16, b_ff2 + i*16,
        W_out, b_out, out, (i == kL - 1) ? 1 : 0);
  }
}